// round 2
// baseline (speedup 1.0000x reference)
#include <cuda_runtime.h>
#include <stdint.h>

// RelationalAttentionLayer: N=20000, E=320000, D=128, H=2, R=3
#define NN 20000
#define EE 320000
#define DD 128
#define HH 2
#define HD 256        // H*D
#define CW 1792       // q(256) | K_r(768) | V_r(768)

// ---------------- device scratch (no cudaMalloc allowed) ----------------
__device__ float g_C[(size_t)NN * CW];       // fused projections
__device__ float g_z[(size_t)NN * HD];       // weighted value accum
__device__ float g_numer[(size_t)EE * HH];   // per-edge numer, CSR order
__device__ int   g_counts[NN];
__device__ int   g_rowoff[NN + 1];
__device__ int   g_cursor[NN];
__device__ int   g_eidx[EE];                 // CSR edge-id list (sorted per node)

// ---------------- small utilities ----------------
__global__ void zero_int_kernel(int* __restrict__ p, int n) {
    int i = blockIdx.x * blockDim.x + threadIdx.x;
    if (i < n) p[i] = 0;
}

__global__ void hist_kernel(const int* __restrict__ edst, int* __restrict__ counts, int E) {
    int i = blockIdx.x * blockDim.x + threadIdx.x;
    if (i < E) atomicAdd(&counts[edst[i]], 1);
}

// single-block exclusive scan of counts -> rowoff (N <= 1024*chunk)
__global__ __launch_bounds__(1024)
void scan_kernel(const int* __restrict__ counts, int* __restrict__ rowoff, int Nn) {
    __shared__ int part[1024];
    int t = threadIdx.x;
    int chunk = (Nn + 1023) / 1024;
    int lo = t * chunk;
    int hi = lo + chunk; if (hi > Nn) hi = Nn;
    int s = 0;
    for (int i = lo; i < hi; i++) s += counts[i];
    part[t] = s;
    __syncthreads();
    for (int off = 1; off < 1024; off <<= 1) {
        int v = (t >= off) ? part[t - off] : 0;
        __syncthreads();
        part[t] += v;
        __syncthreads();
    }
    int run = (t == 0) ? 0 : part[t - 1];
    for (int i = lo; i < hi; i++) { rowoff[i] = run; run += counts[i]; }
    if (t == 1023) rowoff[Nn] = part[1023];
}

__global__ void fill_kernel(const int* __restrict__ edst, int* __restrict__ cursor,
                            int* __restrict__ eidx, int E) {
    int i = blockIdx.x * blockDim.x + threadIdx.x;
    if (i < E) {
        int pos = atomicAdd(&cursor[edst[i]], 1);
        eidx[pos] = i;
    }
}

// deterministic per-node edge order (atomic fill order varies run-to-run)
__global__ void sort_kernel(const int* __restrict__ rowoff, int* __restrict__ eidx, int Nn) {
    int n = blockIdx.x * blockDim.x + threadIdx.x;
    if (n >= Nn) return;
    int lo = rowoff[n], hi = rowoff[n + 1];
    for (int i = lo + 1; i < hi; i++) {
        int v = eidx[i];
        int j = i - 1;
        while (j >= lo && eidx[j] > v) { eidx[j + 1] = eidx[j]; j--; }
        eidx[j + 1] = v;
    }
}

// ---------------- NT GEMM: C[m, colOff+n] = sum_k A[m,k]*B[n,k] ----------------
#define BM 64
#define BN 64
#define BK 16

__global__ __launch_bounds__(256)
void gemm_nt_kernel(const float* __restrict__ A, int lda,
                    const float* __restrict__ B, int ldb,
                    float* __restrict__ C, int ldc, int colOff,
                    int M, int K) {
    __shared__ float As[BK][BM];
    __shared__ float Bs[BK][BN];

    const int bm = blockIdx.y * BM;
    const int bn = blockIdx.x * BN;
    const int tid = threadIdx.x;
    const int tx = tid & 15;
    const int ty = tid >> 4;
    const int lr = tid >> 2;
    const int lc = (tid & 3) * 4;

    float acc[4][4];
#pragma unroll
    for (int i = 0; i < 4; i++)
#pragma unroll
        for (int j = 0; j < 4; j++) acc[i][j] = 0.f;

    for (int k0 = 0; k0 < K; k0 += BK) {
        float4 av = make_float4(0.f, 0.f, 0.f, 0.f);
        int am = bm + lr;
        if (am < M) av = *(const float4*)(A + (size_t)am * lda + k0 + lc);
        As[lc + 0][lr] = av.x;
        As[lc + 1][lr] = av.y;
        As[lc + 2][lr] = av.z;
        As[lc + 3][lr] = av.w;
        float4 bv = *(const float4*)(B + (size_t)(bn + lr) * ldb + k0 + lc);
        Bs[lc + 0][lr] = bv.x;
        Bs[lc + 1][lr] = bv.y;
        Bs[lc + 2][lr] = bv.z;
        Bs[lc + 3][lr] = bv.w;
        __syncthreads();

#pragma unroll
        for (int k = 0; k < BK; k++) {
            float a0 = As[k][ty * 4 + 0];
            float a1 = As[k][ty * 4 + 1];
            float a2 = As[k][ty * 4 + 2];
            float a3 = As[k][ty * 4 + 3];
            float b0 = Bs[k][tx * 4 + 0];
            float b1 = Bs[k][tx * 4 + 1];
            float b2 = Bs[k][tx * 4 + 2];
            float b3 = Bs[k][tx * 4 + 3];
            acc[0][0] += a0 * b0; acc[0][1] += a0 * b1; acc[0][2] += a0 * b2; acc[0][3] += a0 * b3;
            acc[1][0] += a1 * b0; acc[1][1] += a1 * b1; acc[1][2] += a1 * b2; acc[1][3] += a1 * b3;
            acc[2][0] += a2 * b0; acc[2][1] += a2 * b1; acc[2][2] += a2 * b2; acc[2][3] += a2 * b3;
            acc[3][0] += a3 * b0; acc[3][1] += a3 * b1; acc[3][2] += a3 * b2; acc[3][3] += a3 * b3;
        }
        __syncthreads();
    }

#pragma unroll
    for (int i = 0; i < 4; i++) {
        int row = bm + ty * 4 + i;
        if (row < M) {
            float4 v = make_float4(acc[i][0], acc[i][1], acc[i][2], acc[i][3]);
            *(float4*)(C + (size_t)row * ldc + colOff + bn + tx * 4) = v;
        }
    }
}

// ---------------- fused attention: warp per dst node, atomic-free ----------------
// lane owns dims [lane*8, lane*8+8); head = lane>>4
__global__ __launch_bounds__(256)
void node_attn_kernel(const float* __restrict__ C,
                      const int* __restrict__ esrc,
                      const int* __restrict__ erel,
                      const int* __restrict__ rowoff,
                      const int* __restrict__ eidx,
                      float* __restrict__ numer,
                      float* __restrict__ z, int Nn) {
    int n = (blockIdx.x * blockDim.x + threadIdx.x) >> 5;
    int lane = threadIdx.x & 31;
    if (n >= Nn) return;

    int lo = rowoff[n], hi = rowoff[n + 1];
    int h = lane >> 4;

    const float4* qp = (const float4*)(C + (size_t)n * CW) + lane * 2;
    float4 q0 = qp[0], q1 = qp[1];

    // pass 1: scores -> numer (CSR order), accumulate denom per head
    float denom = 0.f;
    for (int p = lo; p < hi; p++) {
        int e = eidx[p];
        int s = esrc[e], r = erel[e];
        const float4* kp = (const float4*)(C + (size_t)s * CW + 256 + (r << 8)) + lane * 2;
        float4 k0 = kp[0], k1 = kp[1];
        float acc = q0.x * k0.x + q0.y * k0.y + q0.z * k0.z + q0.w * k0.w
                  + q1.x * k1.x + q1.y * k1.y + q1.z * k1.z + q1.w * k1.w;
#pragma unroll
        for (int off = 8; off > 0; off >>= 1)
            acc += __shfl_xor_sync(0xffffffffu, acc, off);   // half-warp = head reduce
        float sc = acc * (1.0f / 16.0f);                     // / sqrt(D*H)
        float rl = fmaxf(sc, 0.0f);
        float nu = rl * rl + 1e-10f;
        denom += nu;
        if ((lane & 15) == 0) numer[(size_t)p * HH + h] = nu;
    }

    float inv = (denom > 0.f) ? (1.0f / denom) : 0.f;

    // pass 2: z = sum w * V
    float z0 = 0.f, z1 = 0.f, z2 = 0.f, z3 = 0.f, z4 = 0.f, z5 = 0.f, z6 = 0.f, z7 = 0.f;
    for (int p = lo; p < hi; p++) {
        int e = eidx[p];
        int s = esrc[e], r = erel[e];
        float w = numer[(size_t)p * HH + h] * inv;
        const float4* vp = (const float4*)(C + (size_t)s * CW + 1024 + (r << 8)) + lane * 2;
        float4 v0 = vp[0], v1 = vp[1];
        z0 += w * v0.x; z1 += w * v0.y; z2 += w * v0.z; z3 += w * v0.w;
        z4 += w * v1.x; z5 += w * v1.y; z6 += w * v1.z; z7 += w * v1.w;
    }
    float4* zp = (float4*)(z + (size_t)n * HD) + lane * 2;
    zp[0] = make_float4(z0, z1, z2, z3);
    zp[1] = make_float4(z4, z5, z6, z7);
}

// ---------------- launch ----------------
extern "C" void kernel_launch(void* const* d_in, const int* in_sizes, int n_in,
                              void* d_out, int out_size) {
    const float* nf  = (const float*)d_in[0];
    const float* WQ  = (const float*)d_in[1];
    const float* WK  = (const float*)d_in[2];
    const float* WV  = (const float*)d_in[3];
    const float* WO  = (const float*)d_in[4];
    const int* esrc  = (const int*)d_in[5];
    const int* edst  = (const int*)d_in[6];
    const int* erel  = (const int*)d_in[7];
    float* out = (float*)d_out;

    float *C, *z, *numer;
    int *counts, *rowoff, *cursor, *eidx;
    cudaGetSymbolAddress((void**)&C,      g_C);
    cudaGetSymbolAddress((void**)&z,      g_z);
    cudaGetSymbolAddress((void**)&numer,  g_numer);
    cudaGetSymbolAddress((void**)&counts, g_counts);
    cudaGetSymbolAddress((void**)&rowoff, g_rowoff);
    cudaGetSymbolAddress((void**)&cursor, g_cursor);
    cudaGetSymbolAddress((void**)&eidx,   g_eidx);

    const int E = in_sizes[5];
    const int M = in_sizes[0] / DD;   // = N

    // --- CSR build over edge_dst ---
    zero_int_kernel<<<(M + 255) / 256, 256>>>(counts, M);
    hist_kernel<<<(E + 255) / 256, 256>>>(edst, counts, E);
    scan_kernel<<<1, 1024>>>(counts, rowoff, M);
    cudaMemcpyAsync(cursor, rowoff, M * sizeof(int), cudaMemcpyDeviceToDevice, 0);
    fill_kernel<<<(E + 255) / 256, 256>>>(edst, cursor, eidx, E);
    sort_kernel<<<(M + 255) / 256, 256>>>(rowoff, eidx, M);

    // --- fused projections into C: q | K_r | V_r ---
    {
        dim3 blk(256);
        dim3 gq(256 / BN, (M + BM - 1) / BM);
        gemm_nt_kernel<<<gq, blk>>>(nf, DD, WQ, DD, C, CW, 0,    M, DD);
        dim3 gk(768 / BN, (M + BM - 1) / BM);
        gemm_nt_kernel<<<gk, blk>>>(nf, DD, WK, DD, C, CW, 256,  M, DD);
        gemm_nt_kernel<<<gk, blk>>>(nf, DD, WV, DD, C, CW, 1024, M, DD);
    }

    // --- fused attention (atomic-free, deterministic) ---
    node_attn_kernel<<<(M * 32 + 255) / 256, 256>>>(C, esrc, erel, rowoff, eidx,
                                                    numer, z, M);

    // --- output projection: out = z @ WO^T ---
    {
        dim3 blk(256);
        dim3 go(DD / BN, (M + BM - 1) / BM);
        gemm_nt_kernel<<<go, blk>>>(z, HD, WO, HD, out, DD, 0, M, HD);
    }
}

// round 3
// speedup vs baseline: 1.2392x; 1.2392x over previous
#include <cuda_runtime.h>
#include <stdint.h>

// RelationalAttentionLayer: N=20000, E=320000, D=128, H=2, R=3
#define NN 20000
#define EE 320000
#define DD 128
#define HH 2
#define HD 256        // H*D
#define CW 1792       // q(256) | K_r(768) | V_r(768)

// ---------------- device scratch (no cudaMalloc allowed) ----------------
__device__ float g_C[(size_t)NN * CW];       // fused projections
__device__ float g_z[(size_t)NN * HD];       // weighted value accum
__device__ float g_numer[(size_t)EE * HH];   // per-edge numer, CSR order
__device__ int   g_counts[NN];
__device__ int   g_rowoff[NN + 1];
__device__ int   g_cursor[NN];
__device__ int   g_eidx[EE];                 // CSR edge-id list (sorted per node)

// ---------------- small utilities ----------------
__global__ void zero_int_kernel(int* __restrict__ p, int n) {
    int i = blockIdx.x * blockDim.x + threadIdx.x;
    if (i < n) p[i] = 0;
}

__global__ void hist_kernel(const int* __restrict__ edst, int* __restrict__ counts, int E) {
    int i = blockIdx.x * blockDim.x + threadIdx.x;
    if (i < E) atomicAdd(&counts[edst[i]], 1);
}

__global__ __launch_bounds__(1024)
void scan_kernel(const int* __restrict__ counts, int* __restrict__ rowoff, int Nn) {
    __shared__ int part[1024];
    int t = threadIdx.x;
    int chunk = (Nn + 1023) / 1024;
    int lo = t * chunk;
    int hi = lo + chunk; if (hi > Nn) hi = Nn;
    int s = 0;
    for (int i = lo; i < hi; i++) s += counts[i];
    part[t] = s;
    __syncthreads();
    for (int off = 1; off < 1024; off <<= 1) {
        int v = (t >= off) ? part[t - off] : 0;
        __syncthreads();
        part[t] += v;
        __syncthreads();
    }
    int run = (t == 0) ? 0 : part[t - 1];
    for (int i = lo; i < hi; i++) { rowoff[i] = run; run += counts[i]; }
    if (t == 1023) rowoff[Nn] = part[1023];
}

__global__ void fill_kernel(const int* __restrict__ edst, int* __restrict__ cursor,
                            int* __restrict__ eidx, int E) {
    int i = blockIdx.x * blockDim.x + threadIdx.x;
    if (i < E) {
        int pos = atomicAdd(&cursor[edst[i]], 1);
        eidx[pos] = i;
    }
}

__global__ void sort_kernel(const int* __restrict__ rowoff, int* __restrict__ eidx, int Nn) {
    int n = blockIdx.x * blockDim.x + threadIdx.x;
    if (n >= Nn) return;
    int lo = rowoff[n], hi = rowoff[n + 1];
    for (int i = lo + 1; i < hi; i++) {
        int v = eidx[i];
        int j = i - 1;
        while (j >= lo && eidx[j] > v) { eidx[j + 1] = eidx[j]; j--; }
        eidx[j + 1] = v;
    }
}

// ---------------- tf32 tensor-core NT GEMM ----------------
// C[m, colOff+n] = sum_k A[m,k]*B[n,k]
// block: 256 thr = 8 warps (4 m x 2 n). blocktile 128x64, BK=32.
// warptile 32x32 = 2 m16-tiles x 4 n8-tiles of mma.m16n8k8.
#define TBM 128
#define TBN 64
#define TBK 32
#define APAD 8   // 136 % 32 == 8 -> conflict-free frag loads
#define BPAD 8   // 72  % 32 == 8

__device__ __forceinline__ uint32_t f2tf32(float x) {
    uint32_t r;
    asm("cvt.rna.tf32.f32 %0, %1;" : "=r"(r) : "f"(x));
    return r;
}

__global__ __launch_bounds__(256)
void gemm_tf32_kernel(const float* __restrict__ A, int lda,
                      const float* __restrict__ B, int ldb,
                      float* __restrict__ C, int ldc, int colOff,
                      int M, int K) {
    __shared__ float As[TBK][TBM + APAD];  // [k][m]
    __shared__ float Bs[TBK][TBN + BPAD];  // [k][n]

    const int tid  = threadIdx.x;
    const int warp = tid >> 5;
    const int lane = tid & 31;
    const int g    = lane >> 2;   // groupID 0..7
    const int tg   = lane & 3;    // thread-in-group 0..3
    const int warpM = warp & 3;   // 0..3 -> rows [warpM*32, +32)
    const int warpN = warp >> 2;  // 0..1 -> cols [warpN*32, +32)

    const int bm = blockIdx.y * TBM;
    const int bn = blockIdx.x * TBN;

    float acc[2][4][4];
#pragma unroll
    for (int mt = 0; mt < 2; mt++)
#pragma unroll
        for (int nt = 0; nt < 4; nt++)
#pragma unroll
            for (int c = 0; c < 4; c++) acc[mt][nt][c] = 0.f;

    for (int k0 = 0; k0 < K; k0 += TBK) {
        // stage A tile (128x32) transposed into As[k][m]; 4 float4 per thread
#pragma unroll
        for (int i = 0; i < 4; i++) {
            int idx = tid + i * 256;         // 0..1023
            int row = idx >> 3;              // 0..127
            int kc  = (idx & 7) << 2;        // 0,4,...,28
            float4 v = make_float4(0.f, 0.f, 0.f, 0.f);
            int gr = bm + row;
            if (gr < M) v = *(const float4*)(A + (size_t)gr * lda + k0 + kc);
            As[kc + 0][row] = v.x;
            As[kc + 1][row] = v.y;
            As[kc + 2][row] = v.z;
            As[kc + 3][row] = v.w;
        }
        // stage B tile (64x32) transposed into Bs[k][n]; 2 float4 per thread
#pragma unroll
        for (int i = 0; i < 2; i++) {
            int idx = tid + i * 256;         // 0..511
            int col = idx >> 3;              // 0..63
            int kc  = (idx & 7) << 2;
            float4 v = *(const float4*)(B + (size_t)(bn + col) * ldb + k0 + kc);
            Bs[kc + 0][col] = v.x;
            Bs[kc + 1][col] = v.y;
            Bs[kc + 2][col] = v.z;
            Bs[kc + 3][col] = v.w;
        }
        __syncthreads();

#pragma unroll
        for (int ks = 0; ks < TBK / 8; ks++) {
            int kb = ks * 8;
            uint32_t af[2][4];
#pragma unroll
            for (int mt = 0; mt < 2; mt++) {
                int m0 = warpM * 32 + mt * 16;
                af[mt][0] = f2tf32(As[kb + tg    ][m0 + g    ]);
                af[mt][1] = f2tf32(As[kb + tg    ][m0 + g + 8]);
                af[mt][2] = f2tf32(As[kb + tg + 4][m0 + g    ]);
                af[mt][3] = f2tf32(As[kb + tg + 4][m0 + g + 8]);
            }
            uint32_t bf[4][2];
#pragma unroll
            for (int nt = 0; nt < 4; nt++) {
                int n0 = warpN * 32 + nt * 8;
                bf[nt][0] = f2tf32(Bs[kb + tg    ][n0 + g]);
                bf[nt][1] = f2tf32(Bs[kb + tg + 4][n0 + g]);
            }
#pragma unroll
            for (int mt = 0; mt < 2; mt++)
#pragma unroll
                for (int nt = 0; nt < 4; nt++) {
                    asm volatile(
                        "mma.sync.aligned.m16n8k8.row.col.f32.tf32.tf32.f32 "
                        "{%0,%1,%2,%3}, {%4,%5,%6,%7}, {%8,%9}, {%0,%1,%2,%3};"
                        : "+f"(acc[mt][nt][0]), "+f"(acc[mt][nt][1]),
                          "+f"(acc[mt][nt][2]), "+f"(acc[mt][nt][3])
                        : "r"(af[mt][0]), "r"(af[mt][1]), "r"(af[mt][2]), "r"(af[mt][3]),
                          "r"(bf[nt][0]), "r"(bf[nt][1]));
                }
        }
        __syncthreads();
    }

    // epilogue: c0/c1 -> (row, col..col+1), c2/c3 -> (row+8, col..col+1)
#pragma unroll
    for (int mt = 0; mt < 2; mt++) {
        int row0 = bm + warpM * 32 + mt * 16 + g;
#pragma unroll
        for (int nt = 0; nt < 4; nt++) {
            int col = colOff + bn + warpN * 32 + nt * 8 + tg * 2;
            if (row0 < M)
                *(float2*)(C + (size_t)row0 * ldc + col) =
                    make_float2(acc[mt][nt][0], acc[mt][nt][1]);
            if (row0 + 8 < M)
                *(float2*)(C + (size_t)(row0 + 8) * ldc + col) =
                    make_float2(acc[mt][nt][2], acc[mt][nt][3]);
        }
    }
}

// ---------------- fp32 SIMT NT GEMM (kept for out-projection accuracy) ----------------
#define BM 64
#define BN 64
#define BK 16

__global__ __launch_bounds__(256)
void gemm_nt_kernel(const float* __restrict__ A, int lda,
                    const float* __restrict__ B, int ldb,
                    float* __restrict__ C, int ldc, int colOff,
                    int M, int K) {
    __shared__ float As[BK][BM];
    __shared__ float Bs[BK][BN];

    const int bm = blockIdx.y * BM;
    const int bn = blockIdx.x * BN;
    const int tid = threadIdx.x;
    const int tx = tid & 15;
    const int ty = tid >> 4;
    const int lr = tid >> 2;
    const int lc = (tid & 3) * 4;

    float acc[4][4];
#pragma unroll
    for (int i = 0; i < 4; i++)
#pragma unroll
        for (int j = 0; j < 4; j++) acc[i][j] = 0.f;

    for (int k0 = 0; k0 < K; k0 += BK) {
        float4 av = make_float4(0.f, 0.f, 0.f, 0.f);
        int am = bm + lr;
        if (am < M) av = *(const float4*)(A + (size_t)am * lda + k0 + lc);
        As[lc + 0][lr] = av.x;
        As[lc + 1][lr] = av.y;
        As[lc + 2][lr] = av.z;
        As[lc + 3][lr] = av.w;
        float4 bv = *(const float4*)(B + (size_t)(bn + lr) * ldb + k0 + lc);
        Bs[lc + 0][lr] = bv.x;
        Bs[lc + 1][lr] = bv.y;
        Bs[lc + 2][lr] = bv.z;
        Bs[lc + 3][lr] = bv.w;
        __syncthreads();

#pragma unroll
        for (int k = 0; k < BK; k++) {
            float a0 = As[k][ty * 4 + 0];
            float a1 = As[k][ty * 4 + 1];
            float a2 = As[k][ty * 4 + 2];
            float a3 = As[k][ty * 4 + 3];
            float b0 = Bs[k][tx * 4 + 0];
            float b1 = Bs[k][tx * 4 + 1];
            float b2 = Bs[k][tx * 4 + 2];
            float b3 = Bs[k][tx * 4 + 3];
            acc[0][0] += a0 * b0; acc[0][1] += a0 * b1; acc[0][2] += a0 * b2; acc[0][3] += a0 * b3;
            acc[1][0] += a1 * b0; acc[1][1] += a1 * b1; acc[1][2] += a1 * b2; acc[1][3] += a1 * b3;
            acc[2][0] += a2 * b0; acc[2][1] += a2 * b1; acc[2][2] += a2 * b2; acc[2][3] += a2 * b3;
            acc[3][0] += a3 * b0; acc[3][1] += a3 * b1; acc[3][2] += a3 * b2; acc[3][3] += a3 * b3;
        }
        __syncthreads();
    }

#pragma unroll
    for (int i = 0; i < 4; i++) {
        int row = bm + ty * 4 + i;
        if (row < M) {
            float4 v = make_float4(acc[i][0], acc[i][1], acc[i][2], acc[i][3]);
            *(float4*)(C + (size_t)row * ldc + colOff + bn + tx * 4) = v;
        }
    }
}

// ---------------- fused attention: warp per dst node, atomic-free ----------------
__global__ __launch_bounds__(256)
void node_attn_kernel(const float* __restrict__ C,
                      const int* __restrict__ esrc,
                      const int* __restrict__ erel,
                      const int* __restrict__ rowoff,
                      const int* __restrict__ eidx,
                      float* __restrict__ numer,
                      float* __restrict__ z, int Nn) {
    int n = (blockIdx.x * blockDim.x + threadIdx.x) >> 5;
    int lane = threadIdx.x & 31;
    if (n >= Nn) return;

    int lo = rowoff[n], hi = rowoff[n + 1];
    int h = lane >> 4;

    const float4* qp = (const float4*)(C + (size_t)n * CW) + lane * 2;
    float4 q0 = qp[0], q1 = qp[1];

    float denom = 0.f;
    for (int p = lo; p < hi; p++) {
        int e = eidx[p];
        int s = esrc[e], r = erel[e];
        const float4* kp = (const float4*)(C + (size_t)s * CW + 256 + (r << 8)) + lane * 2;
        float4 k0 = kp[0], k1 = kp[1];
        float acc = q0.x * k0.x + q0.y * k0.y + q0.z * k0.z + q0.w * k0.w
                  + q1.x * k1.x + q1.y * k1.y + q1.z * k1.z + q1.w * k1.w;
#pragma unroll
        for (int off = 8; off > 0; off >>= 1)
            acc += __shfl_xor_sync(0xffffffffu, acc, off);
        float sc = acc * (1.0f / 16.0f);
        float rl = fmaxf(sc, 0.0f);
        float nu = rl * rl + 1e-10f;
        denom += nu;
        if ((lane & 15) == 0) numer[(size_t)p * HH + h] = nu;
    }

    float inv = (denom > 0.f) ? (1.0f / denom) : 0.f;

    float z0 = 0.f, z1 = 0.f, z2 = 0.f, z3 = 0.f, z4 = 0.f, z5 = 0.f, z6 = 0.f, z7 = 0.f;
    for (int p = lo; p < hi; p++) {
        int e = eidx[p];
        int s = esrc[e], r = erel[e];
        float w = numer[(size_t)p * HH + h] * inv;
        const float4* vp = (const float4*)(C + (size_t)s * CW + 1024 + (r << 8)) + lane * 2;
        float4 v0 = vp[0], v1 = vp[1];
        z0 += w * v0.x; z1 += w * v0.y; z2 += w * v0.z; z3 += w * v0.w;
        z4 += w * v1.x; z5 += w * v1.y; z6 += w * v1.z; z7 += w * v1.w;
    }
    float4* zp = (float4*)(z + (size_t)n * HD) + lane * 2;
    zp[0] = make_float4(z0, z1, z2, z3);
    zp[1] = make_float4(z4, z5, z6, z7);
}

// ---------------- launch ----------------
extern "C" void kernel_launch(void* const* d_in, const int* in_sizes, int n_in,
                              void* d_out, int out_size) {
    const float* nf  = (const float*)d_in[0];
    const float* WQ  = (const float*)d_in[1];
    const float* WK  = (const float*)d_in[2];
    const float* WV  = (const float*)d_in[3];
    const float* WO  = (const float*)d_in[4];
    const int* esrc  = (const int*)d_in[5];
    const int* edst  = (const int*)d_in[6];
    const int* erel  = (const int*)d_in[7];
    float* out = (float*)d_out;

    float *C, *z, *numer;
    int *counts, *rowoff, *cursor, *eidx;
    cudaGetSymbolAddress((void**)&C,      g_C);
    cudaGetSymbolAddress((void**)&z,      g_z);
    cudaGetSymbolAddress((void**)&numer,  g_numer);
    cudaGetSymbolAddress((void**)&counts, g_counts);
    cudaGetSymbolAddress((void**)&rowoff, g_rowoff);
    cudaGetSymbolAddress((void**)&cursor, g_cursor);
    cudaGetSymbolAddress((void**)&eidx,   g_eidx);

    const int E = in_sizes[5];
    const int M = in_sizes[0] / DD;   // = N

    // --- CSR build over edge_dst ---
    zero_int_kernel<<<(M + 255) / 256, 256>>>(counts, M);
    hist_kernel<<<(E + 255) / 256, 256>>>(edst, counts, E);
    scan_kernel<<<1, 1024>>>(counts, rowoff, M);
    cudaMemcpyAsync(cursor, rowoff, M * sizeof(int), cudaMemcpyDeviceToDevice, 0);
    fill_kernel<<<(E + 255) / 256, 256>>>(edst, cursor, eidx, E);
    sort_kernel<<<(M + 255) / 256, 256>>>(rowoff, eidx, M);

    // --- fused projections into C (tf32 tensor cores): q | K_r | V_r ---
    {
        dim3 blk(256);
        dim3 gq(256 / TBN, (M + TBM - 1) / TBM);
        gemm_tf32_kernel<<<gq, blk>>>(nf, DD, WQ, DD, C, CW, 0,    M, DD);
        dim3 gk(768 / TBN, (M + TBM - 1) / TBM);
        gemm_tf32_kernel<<<gk, blk>>>(nf, DD, WK, DD, C, CW, 256,  M, DD);
        gemm_tf32_kernel<<<gk, blk>>>(nf, DD, WV, DD, C, CW, 1024, M, DD);
    }

    // --- fused attention (atomic-free, deterministic) ---
    node_attn_kernel<<<(M * 32 + 255) / 256, 256>>>(C, esrc, erel, rowoff, eidx,
                                                    numer, z, M);

    // --- output projection (fp32 SIMT for accuracy): out = z @ WO^T ---
    {
        dim3 blk(256);
        dim3 go(DD / BN, (M + BM - 1) / BM);
        gemm_nt_kernel<<<go, blk>>>(z, HD, WO, HD, out, DD, 0, M, HD);
    }
}

// round 6
// speedup vs baseline: 1.8350x; 1.4809x over previous
#include <cuda_runtime.h>
#include <stdint.h>

// RelationalAttentionLayer: N=20000, E=320000, D=128, H=2, R=3
#define NN 20000
#define EE 320000
#define DD 128
#define HH 2
#define HD 256        // H*D
#define CW 1792       // q(256) | K_r(768) | V_r(768)

// ---------------- device scratch (no cudaMalloc allowed) ----------------
__device__ float g_C[(size_t)NN * CW];       // fused projections
__device__ float g_z[(size_t)NN * HD];       // weighted value accum
__device__ int   g_counts[NN];
__device__ int   g_rowoff[NN + 1];
__device__ int   g_cursor[NN];
__device__ int   g_eidx[EE];                 // CSR edge-id list (sorted per node)
__device__ int   g_srcrel[EE];               // packed src|rel<<20 in CSR order

// ---------------- small utilities ----------------
__global__ void zero_int_kernel(int* __restrict__ p, int n) {
    int i = blockIdx.x * blockDim.x + threadIdx.x;
    if (i < n) p[i] = 0;
}

__global__ void hist_kernel(const int* __restrict__ edst, int* __restrict__ counts, int E) {
    int i = blockIdx.x * blockDim.x + threadIdx.x;
    if (i < E) atomicAdd(&counts[edst[i]], 1);
}

__global__ __launch_bounds__(1024)
void scan_kernel(const int* __restrict__ counts, int* __restrict__ rowoff, int Nn) {
    __shared__ int part[1024];
    int t = threadIdx.x;
    int chunk = (Nn + 1023) / 1024;
    int lo = t * chunk;
    int hi = lo + chunk; if (hi > Nn) hi = Nn;
    int s = 0;
    for (int i = lo; i < hi; i++) s += counts[i];
    part[t] = s;
    __syncthreads();
    for (int off = 1; off < 1024; off <<= 1) {
        int v = (t >= off) ? part[t - off] : 0;
        __syncthreads();
        part[t] += v;
        __syncthreads();
    }
    int run = (t == 0) ? 0 : part[t - 1];
    for (int i = lo; i < hi; i++) { rowoff[i] = run; run += counts[i]; }
    if (t == 1023) rowoff[Nn] = part[1023];
}

__global__ void fill_kernel(const int* __restrict__ edst, int* __restrict__ cursor,
                            int* __restrict__ eidx, int E) {
    int i = blockIdx.x * blockDim.x + threadIdx.x;
    if (i < E) {
        int pos = atomicAdd(&cursor[edst[i]], 1);
        eidx[pos] = i;
    }
}

// deterministic per-node edge order
__global__ void sort_kernel(const int* __restrict__ rowoff, int* __restrict__ eidx, int Nn) {
    int n = blockIdx.x * blockDim.x + threadIdx.x;
    if (n >= Nn) return;
    int lo = rowoff[n], hi = rowoff[n + 1];
    for (int i = lo + 1; i < hi; i++) {
        int v = eidx[i];
        int j = i - 1;
        while (j >= lo && eidx[j] > v) { eidx[j + 1] = eidx[j]; j--; }
        eidx[j + 1] = v;
    }
}

// pack (src, rel) in CSR order: removes the eidx->esrc/erel dependent-load chain
__global__ void pack_kernel(const int* __restrict__ eidx,
                            const int* __restrict__ esrc,
                            const int* __restrict__ erel,
                            int* __restrict__ srcrel, int E) {
    int p = blockIdx.x * blockDim.x + threadIdx.x;
    if (p < E) {
        int e = eidx[p];
        srcrel[p] = esrc[e] | (erel[e] << 20);
    }
}

// ---------------- fused double-buffered tf32 QKV GEMM ----------------
// C[:, 0:1792] = nf @ [WQ|WK|WV]^T. blocktile 128x64, BK=32, 2-stage cp.async.
// smem row-major [m][k] stride 36 -> conflict-free frag loads.
#define TBM 128
#define TBN 64
#define TBK 32
#define TSTR 36

__device__ __forceinline__ uint32_t f2tf32(float x) {
    uint32_t r;
    asm("cvt.rna.tf32.f32 %0, %1;" : "=r"(r) : "f"(x));
    return r;
}

__device__ __forceinline__ void cp_async16(void* dst, const void* src, bool pred) {
    uint32_t d = (uint32_t)__cvta_generic_to_shared(dst);
    int sz = pred ? 16 : 0;
    asm volatile("cp.async.cg.shared.global [%0], [%1], 16, %2;"
                 :: "r"(d), "l"(src), "r"(sz));
}

__global__ __launch_bounds__(256)
void gemm_qkv_tf32_kernel(const float* __restrict__ A,
                          const float* __restrict__ WQ,
                          const float* __restrict__ WK,
                          const float* __restrict__ WV,
                          float* __restrict__ C, int M) {
    __shared__ float As[2][TBM][TSTR];
    __shared__ float Bs[2][TBN][TSTR];

    const int tid  = threadIdx.x;
    const int warp = tid >> 5;
    const int lane = tid & 31;
    const int g    = lane >> 2;
    const int tg   = lane & 3;
    const int warpM = warp & 3;
    const int warpN = warp >> 2;

    const int bm = blockIdx.y * TBM;

    const float* Bp;
    int bn, coff;
    if (blockIdx.x < 4)       { Bp = WQ; bn = blockIdx.x * TBN;        coff = 0; }
    else if (blockIdx.x < 16) { Bp = WK; bn = (blockIdx.x - 4) * TBN;  coff = 256; }
    else                      { Bp = WV; bn = (blockIdx.x - 16) * TBN; coff = 1024; }

    float acc[2][4][4];
#pragma unroll
    for (int mt = 0; mt < 2; mt++)
#pragma unroll
        for (int nt = 0; nt < 4; nt++)
#pragma unroll
            for (int c = 0; c < 4; c++) acc[mt][nt][c] = 0.f;

    auto stage = [&](int st, int k0) {
#pragma unroll
        for (int i = 0; i < 4; i++) {
            int idx = tid + i * 256;
            int row = idx >> 3;
            int kc  = (idx & 7) << 2;
            int gr  = bm + row;
            cp_async16(&As[st][row][kc], A + (size_t)gr * DD + k0 + kc, gr < M);
        }
#pragma unroll
        for (int i = 0; i < 2; i++) {
            int idx = tid + i * 256;
            int col = idx >> 3;
            int kc  = (idx & 7) << 2;
            cp_async16(&Bs[st][col][kc], Bp + (size_t)(bn + col) * DD + k0 + kc, true);
        }
        asm volatile("cp.async.commit_group;");
    };

    const int KT = DD / TBK;   // 4
    stage(0, 0);

#pragma unroll
    for (int kt = 0; kt < KT; kt++) {
        if (kt + 1 < KT) {
            stage((kt + 1) & 1, (kt + 1) * TBK);
            asm volatile("cp.async.wait_group 1;");
        } else {
            asm volatile("cp.async.wait_group 0;");
        }
        __syncthreads();

        int st = kt & 1;
#pragma unroll
        for (int ks = 0; ks < TBK / 8; ks++) {
            int kb = ks * 8;
            uint32_t af[2][4];
#pragma unroll
            for (int mt = 0; mt < 2; mt++) {
                int m0 = warpM * 32 + mt * 16;
                af[mt][0] = f2tf32(As[st][m0 + g    ][kb + tg    ]);
                af[mt][1] = f2tf32(As[st][m0 + g + 8][kb + tg    ]);
                af[mt][2] = f2tf32(As[st][m0 + g    ][kb + tg + 4]);
                af[mt][3] = f2tf32(As[st][m0 + g + 8][kb + tg + 4]);
            }
            uint32_t bf[4][2];
#pragma unroll
            for (int nt = 0; nt < 4; nt++) {
                int n0 = warpN * 32 + nt * 8;
                bf[nt][0] = f2tf32(Bs[st][n0 + g][kb + tg    ]);
                bf[nt][1] = f2tf32(Bs[st][n0 + g][kb + tg + 4]);
            }
#pragma unroll
            for (int mt = 0; mt < 2; mt++)
#pragma unroll
                for (int nt = 0; nt < 4; nt++) {
                    asm volatile(
                        "mma.sync.aligned.m16n8k8.row.col.f32.tf32.tf32.f32 "
                        "{%0,%1,%2,%3}, {%4,%5,%6,%7}, {%8,%9}, {%0,%1,%2,%3};"
                        : "+f"(acc[mt][nt][0]), "+f"(acc[mt][nt][1]),
                          "+f"(acc[mt][nt][2]), "+f"(acc[mt][nt][3])
                        : "r"(af[mt][0]), "r"(af[mt][1]), "r"(af[mt][2]), "r"(af[mt][3]),
                          "r"(bf[nt][0]), "r"(bf[nt][1]));
                }
        }
        __syncthreads();
    }

#pragma unroll
    for (int mt = 0; mt < 2; mt++) {
        int row0 = bm + warpM * 32 + mt * 16 + g;
#pragma unroll
        for (int nt = 0; nt < 4; nt++) {
            int col = coff + bn + warpN * 32 + nt * 8 + tg * 2;
            if (row0 < M)
                *(float2*)(C + (size_t)row0 * CW + col) =
                    make_float2(acc[mt][nt][0], acc[mt][nt][1]);
            if (row0 + 8 < M)
                *(float2*)(C + (size_t)(row0 + 8) * CW + col) =
                    make_float2(acc[mt][nt][2], acc[mt][nt][3]);
        }
    }
}

// ---------------- fp32 SIMT NT GEMM (out-projection, accuracy) ----------------
#define BM 64
#define BN 64
#define BK 16

__global__ __launch_bounds__(256)
void gemm_nt_kernel(const float* __restrict__ A, int lda,
                    const float* __restrict__ B, int ldb,
                    float* __restrict__ C, int ldc,
                    int M, int K) {
    __shared__ float As[BK][BM];
    __shared__ float Bs[BK][BN];

    const int bm = blockIdx.y * BM;
    const int bn = blockIdx.x * BN;
    const int tid = threadIdx.x;
    const int tx = tid & 15;
    const int ty = tid >> 4;
    const int lr = tid >> 2;
    const int lc = (tid & 3) * 4;

    float acc[4][4];
#pragma unroll
    for (int i = 0; i < 4; i++)
#pragma unroll
        for (int j = 0; j < 4; j++) acc[i][j] = 0.f;

    for (int k0 = 0; k0 < K; k0 += BK) {
        float4 av = make_float4(0.f, 0.f, 0.f, 0.f);
        int am = bm + lr;
        if (am < M) av = *(const float4*)(A + (size_t)am * lda + k0 + lc);
        As[lc + 0][lr] = av.x;
        As[lc + 1][lr] = av.y;
        As[lc + 2][lr] = av.z;
        As[lc + 3][lr] = av.w;
        float4 bv = *(const float4*)(B + (size_t)(bn + lr) * ldb + k0 + lc);
        Bs[lc + 0][lr] = bv.x;
        Bs[lc + 1][lr] = bv.y;
        Bs[lc + 2][lr] = bv.z;
        Bs[lc + 3][lr] = bv.w;
        __syncthreads();

#pragma unroll
        for (int k = 0; k < BK; k++) {
            float a0 = As[k][ty * 4 + 0];
            float a1 = As[k][ty * 4 + 1];
            float a2 = As[k][ty * 4 + 2];
            float a3 = As[k][ty * 4 + 3];
            float b0 = Bs[k][tx * 4 + 0];
            float b1 = Bs[k][tx * 4 + 1];
            float b2 = Bs[k][tx * 4 + 2];
            float b3 = Bs[k][tx * 4 + 3];
            acc[0][0] += a0 * b0; acc[0][1] += a0 * b1; acc[0][2] += a0 * b2; acc[0][3] += a0 * b3;
            acc[1][0] += a1 * b0; acc[1][1] += a1 * b1; acc[1][2] += a1 * b2; acc[1][3] += a1 * b3;
            acc[2][0] += a2 * b0; acc[2][1] += a2 * b1; acc[2][2] += a2 * b2; acc[2][3] += a2 * b3;
            acc[3][0] += a3 * b0; acc[3][1] += a3 * b1; acc[3][2] += a3 * b2; acc[3][3] += a3 * b3;
        }
        __syncthreads();
    }

#pragma unroll
    for (int i = 0; i < 4; i++) {
        int row = bm + ty * 4 + i;
        if (row < M) {
            float4 v = make_float4(acc[i][0], acc[i][1], acc[i][2], acc[i][3]);
            *(float4*)(C + (size_t)row * ldc + bn + tx * 4) = v;
        }
    }
}

// ---------------- fused attention: single pass, warp per dst node ----------------
// z[n] = (sum_e nu_e * V_e) / (sum_e nu_e), per head. Atomic-free.
__global__ __launch_bounds__(256)
void node_attn_kernel(const float* __restrict__ C,
                      const int* __restrict__ srcrel,
                      const int* __restrict__ rowoff,
                      float* __restrict__ z, int Nn) {
    int n = (blockIdx.x * blockDim.x + threadIdx.x) >> 5;
    int lane = threadIdx.x & 31;
    if (n >= Nn) return;

    int lo = rowoff[n], hi = rowoff[n + 1];

    const float4* qp = (const float4*)(C + (size_t)n * CW) + lane * 2;
    float4 q0 = qp[0], q1 = qp[1];

    float denom = 0.f;
    float z0 = 0.f, z1 = 0.f, z2 = 0.f, z3 = 0.f, z4 = 0.f, z5 = 0.f, z6 = 0.f, z7 = 0.f;

    for (int p = lo; p < hi; p++) {
        int pr = srcrel[p];
        int s = pr & 0xFFFFF;
        int r = pr >> 20;
        const float* base = C + (size_t)s * CW + (r << 8);
        const float4* kp = (const float4*)(base + 256) + lane * 2;
        const float4* vp = (const float4*)(base + 1024) + lane * 2;
        float4 k0 = kp[0], k1 = kp[1];
        float4 v0 = vp[0], v1 = vp[1];

        float acc = q0.x * k0.x + q0.y * k0.y + q0.z * k0.z + q0.w * k0.w
                  + q1.x * k1.x + q1.y * k1.y + q1.z * k1.z + q1.w * k1.w;
#pragma unroll
        for (int off = 8; off > 0; off >>= 1)
            acc += __shfl_xor_sync(0xffffffffu, acc, off);   // per-head (16-lane) sum

        float sc = acc * (1.0f / 16.0f);                     // / sqrt(D*H)
        float rl = fmaxf(sc, 0.0f);
        float nu = rl * rl + 1e-10f;
        denom += nu;

        z0 += nu * v0.x; z1 += nu * v0.y; z2 += nu * v0.z; z3 += nu * v0.w;
        z4 += nu * v1.x; z5 += nu * v1.y; z6 += nu * v1.z; z7 += nu * v1.w;
    }

    float inv = (denom > 0.f) ? (1.0f / denom) : 0.f;
    float4* zp = (float4*)(z + (size_t)n * HD) + lane * 2;
    zp[0] = make_float4(z0 * inv, z1 * inv, z2 * inv, z3 * inv);
    zp[1] = make_float4(z4 * inv, z5 * inv, z6 * inv, z7 * inv);
}

// ---------------- launch ----------------
extern "C" void kernel_launch(void* const* d_in, const int* in_sizes, int n_in,
                              void* d_out, int out_size) {
    const float* nf  = (const float*)d_in[0];
    const float* WQ  = (const float*)d_in[1];
    const float* WK  = (const float*)d_in[2];
    const float* WV  = (const float*)d_in[3];
    const float* WO  = (const float*)d_in[4];
    const int* esrc  = (const int*)d_in[5];
    const int* edst  = (const int*)d_in[6];
    const int* erel  = (const int*)d_in[7];
    float* out = (float*)d_out;

    float *C, *z;
    int *counts, *rowoff, *cursor, *eidx, *srcrel;
    cudaGetSymbolAddress((void**)&C,      g_C);
    cudaGetSymbolAddress((void**)&z,      g_z);
    cudaGetSymbolAddress((void**)&counts, g_counts);
    cudaGetSymbolAddress((void**)&rowoff, g_rowoff);
    cudaGetSymbolAddress((void**)&cursor, g_cursor);
    cudaGetSymbolAddress((void**)&eidx,   g_eidx);
    cudaGetSymbolAddress((void**)&srcrel, g_srcrel);

    const int E = in_sizes[5];
    const int M = in_sizes[0] / DD;   // = N

    // --- CSR build over edge_dst ---
    zero_int_kernel<<<(M + 255) / 256, 256>>>(counts, M);
    hist_kernel<<<(E + 255) / 256, 256>>>(edst, counts, E);
    scan_kernel<<<1, 1024>>>(counts, rowoff, M);
    cudaMemcpyAsync(cursor, rowoff, M * sizeof(int), cudaMemcpyDeviceToDevice, 0);
    fill_kernel<<<(E + 255) / 256, 256>>>(edst, cursor, eidx, E);
    sort_kernel<<<(M + 255) / 256, 256>>>(rowoff, eidx, M);
    pack_kernel<<<(E + 255) / 256, 256>>>(eidx, esrc, erel, srcrel, E);

    // --- fused QKV projection (tf32, double-buffered, one launch) ---
    {
        dim3 blk(256);
        dim3 grd(28, (M + TBM - 1) / TBM);   // 28 = (256+768+768)/64
        gemm_qkv_tf32_kernel<<<grd, blk>>>(nf, WQ, WK, WV, C, M);
    }

    // --- fused single-pass attention (atomic-free, deterministic) ---
    node_attn_kernel<<<(M * 32 + 255) / 256, 256>>>(C, srcrel, rowoff, z, M);

    // --- output projection (fp32 SIMT): out = z @ WO^T ---
    {
        dim3 blk(256);
        dim3 go(DD / BN, (M + BM - 1) / BM);
        gemm_nt_kernel<<<go, blk>>>(z, HD, WO, HD, out, DD, M, HD);
    }
}

// round 12
// speedup vs baseline: 1.8511x; 1.0088x over previous
#include <cuda_runtime.h>
#include <stdint.h>

// RelationalAttentionLayer: N=20000, E=320000, D=128, H=2, R=3
#define NN 20000
#define EE 320000
#define DD 128
#define HH 2
#define HD 256        // H*D
#define CW 1792       // q(256) | K_r(768) | V_r(768)

// ---------------- device scratch (no cudaMalloc allowed) ----------------
__device__ float g_C[(size_t)NN * CW];       // fused projections
__device__ float g_z[(size_t)NN * HD];       // weighted value accum
__device__ int   g_counts[NN];
__device__ int   g_rowoff[NN + 1];
__device__ int   g_cursor[NN];
__device__ int   g_eidx[EE];                 // CSR edge-id list (sorted per node)
__device__ int   g_srcrel[EE];               // packed src|rel<<20 in CSR order

// ---------------- small utilities ----------------
__global__ void zero_int_kernel(int* __restrict__ p, int n) {
    int i = blockIdx.x * blockDim.x + threadIdx.x;
    if (i < n) p[i] = 0;
}

__global__ void hist_kernel(const int* __restrict__ edst, int* __restrict__ counts, int E) {
    int i = blockIdx.x * blockDim.x + threadIdx.x;
    if (i < E) atomicAdd(&counts[edst[i]], 1);
}

// exclusive scan of counts -> rowoff AND cursor (cursor = working copy for fill)
__global__ __launch_bounds__(1024)
void scan_kernel(const int* __restrict__ counts, int* __restrict__ rowoff,
                 int* __restrict__ cursor, int Nn) {
    __shared__ int part[1024];
    int t = threadIdx.x;
    int chunk = (Nn + 1023) / 1024;
    int lo = t * chunk;
    int hi = lo + chunk; if (hi > Nn) hi = Nn;
    int s = 0;
    for (int i = lo; i < hi; i++) s += counts[i];
    part[t] = s;
    __syncthreads();
    for (int off = 1; off < 1024; off <<= 1) {
        int v = (t >= off) ? part[t - off] : 0;
        __syncthreads();
        part[t] += v;
        __syncthreads();
    }
    int run = (t == 0) ? 0 : part[t - 1];
    for (int i = lo; i < hi; i++) {
        rowoff[i] = run;
        cursor[i] = run;
        run += counts[i];
    }
    if (t == 1023) rowoff[Nn] = part[1023];
}

__global__ void fill_kernel(const int* __restrict__ edst, int* __restrict__ cursor,
                            int* __restrict__ eidx, int E) {
    int i = blockIdx.x * blockDim.x + threadIdx.x;
    if (i < E) {
        int pos = atomicAdd(&cursor[edst[i]], 1);
        eidx[pos] = i;
    }
}

// deterministic per-node edge order + srcrel pack (fused, one pass)
__global__ void sortpack_kernel(const int* __restrict__ rowoff,
                                int* __restrict__ eidx,
                                const int* __restrict__ esrc,
                                const int* __restrict__ erel,
                                int* __restrict__ srcrel, int Nn) {
    int n = blockIdx.x * blockDim.x + threadIdx.x;
    if (n >= Nn) return;
    int lo = rowoff[n], hi = rowoff[n + 1];
    for (int i = lo + 1; i < hi; i++) {
        int v = eidx[i];
        int j = i - 1;
        while (j >= lo && eidx[j] > v) { eidx[j + 1] = eidx[j]; j--; }
        eidx[j + 1] = v;
    }
    for (int i = lo; i < hi; i++) {
        int e = eidx[i];
        srcrel[i] = esrc[e] | (erel[e] << 20);
    }
}

// ---------------- common tf32 helpers ----------------
#define TBM 128
#define TBN 64
#define TBK 32
#define TSTR 36

__device__ __forceinline__ uint32_t f2tf32(float x) {
    uint32_t r;
    asm("cvt.rna.tf32.f32 %0, %1;" : "=r"(r) : "f"(x));
    return r;
}

__device__ __forceinline__ void cp_async16(void* dst, const void* src, bool pred) {
    uint32_t d = (uint32_t)__cvta_generic_to_shared(dst);
    int sz = pred ? 16 : 0;
    asm volatile("cp.async.cg.shared.global [%0], [%1], 16, %2;"
                 :: "r"(d), "l"(src), "r"(sz));
}

#define MMA_TF32(ACC, A0, A1, A2, A3, B0, B1)                              \
    asm volatile(                                                          \
        "mma.sync.aligned.m16n8k8.row.col.f32.tf32.tf32.f32 "              \
        "{%0,%1,%2,%3}, {%4,%5,%6,%7}, {%8,%9}, {%0,%1,%2,%3};"            \
        : "+f"((ACC)[0]), "+f"((ACC)[1]), "+f"((ACC)[2]), "+f"((ACC)[3])   \
        : "r"(A0), "r"(A1), "r"(A2), "r"(A3), "r"(B0), "r"(B1))

// ---------------- fused double-buffered tf32 QKV GEMM ----------------
// C[:, 0:1792] = nf @ [WQ|WK|WV]^T. blocktile 128x64, BK=32, 2-stage cp.async.
__global__ __launch_bounds__(256)
void gemm_qkv_tf32_kernel(const float* __restrict__ A,
                          const float* __restrict__ WQ,
                          const float* __restrict__ WK,
                          const float* __restrict__ WV,
                          float* __restrict__ C, int M) {
    __shared__ float As[2][TBM][TSTR];
    __shared__ float Bs[2][TBN][TSTR];

    const int tid  = threadIdx.x;
    const int warp = tid >> 5;
    const int lane = tid & 31;
    const int g    = lane >> 2;
    const int tg   = lane & 3;
    const int warpM = warp & 3;
    const int warpN = warp >> 2;

    const int bm = blockIdx.y * TBM;

    const float* Bp;
    int bn, coff;
    if (blockIdx.x < 4)       { Bp = WQ; bn = blockIdx.x * TBN;        coff = 0; }
    else if (blockIdx.x < 16) { Bp = WK; bn = (blockIdx.x - 4) * TBN;  coff = 256; }
    else                      { Bp = WV; bn = (blockIdx.x - 16) * TBN; coff = 1024; }

    float acc[2][4][4];
#pragma unroll
    for (int mt = 0; mt < 2; mt++)
#pragma unroll
        for (int nt = 0; nt < 4; nt++)
#pragma unroll
            for (int c = 0; c < 4; c++) acc[mt][nt][c] = 0.f;

    auto stage = [&](int st, int k0) {
#pragma unroll
        for (int i = 0; i < 4; i++) {
            int idx = tid + i * 256;
            int row = idx >> 3;
            int kc  = (idx & 7) << 2;
            int gr  = bm + row;
            cp_async16(&As[st][row][kc], A + (size_t)gr * DD + k0 + kc, gr < M);
        }
#pragma unroll
        for (int i = 0; i < 2; i++) {
            int idx = tid + i * 256;
            int col = idx >> 3;
            int kc  = (idx & 7) << 2;
            cp_async16(&Bs[st][col][kc], Bp + (size_t)(bn + col) * DD + k0 + kc, true);
        }
        asm volatile("cp.async.commit_group;");
    };

    const int KT = DD / TBK;   // 4
    stage(0, 0);

#pragma unroll
    for (int kt = 0; kt < KT; kt++) {
        if (kt + 1 < KT) {
            stage((kt + 1) & 1, (kt + 1) * TBK);
            asm volatile("cp.async.wait_group 1;");
        } else {
            asm volatile("cp.async.wait_group 0;");
        }
        __syncthreads();

        int st = kt & 1;
#pragma unroll
        for (int ks = 0; ks < TBK / 8; ks++) {
            int kb = ks * 8;
            uint32_t af[2][4];
#pragma unroll
            for (int mt = 0; mt < 2; mt++) {
                int m0 = warpM * 32 + mt * 16;
                af[mt][0] = f2tf32(As[st][m0 + g    ][kb + tg    ]);
                af[mt][1] = f2tf32(As[st][m0 + g + 8][kb + tg    ]);
                af[mt][2] = f2tf32(As[st][m0 + g    ][kb + tg + 4]);
                af[mt][3] = f2tf32(As[st][m0 + g + 8][kb + tg + 4]);
            }
            uint32_t bf[4][2];
#pragma unroll
            for (int nt = 0; nt < 4; nt++) {
                int n0 = warpN * 32 + nt * 8;
                bf[nt][0] = f2tf32(Bs[st][n0 + g][kb + tg    ]);
                bf[nt][1] = f2tf32(Bs[st][n0 + g][kb + tg + 4]);
            }
#pragma unroll
            for (int mt = 0; mt < 2; mt++)
#pragma unroll
                for (int nt = 0; nt < 4; nt++)
                    MMA_TF32(acc[mt][nt], af[mt][0], af[mt][1], af[mt][2], af[mt][3],
                             bf[nt][0], bf[nt][1]);
        }
        __syncthreads();
    }

#pragma unroll
    for (int mt = 0; mt < 2; mt++) {
        int row0 = bm + warpM * 32 + mt * 16 + g;
#pragma unroll
        for (int nt = 0; nt < 4; nt++) {
            int col = coff + bn + warpN * 32 + nt * 8 + tg * 2;
            if (row0 < M)
                *(float2*)(C + (size_t)row0 * CW + col) =
                    make_float2(acc[mt][nt][0], acc[mt][nt][1]);
            if (row0 + 8 < M)
                *(float2*)(C + (size_t)(row0 + 8) * CW + col) =
                    make_float2(acc[mt][nt][2], acc[mt][nt][3]);
        }
    }
}

// ---------------- out-projection: 3xTF32 tensor GEMM (fp32-level accuracy) ----
// out[m,n] = sum_k z[m,k] * WO[n,k].  M=20000, N=128, K=256.
// x = big + small; acc += bs + sb + bb  (ss term ~2^-22, dropped)
__global__ __launch_bounds__(256)
void gemm_out_tf32x3_kernel(const float* __restrict__ A,   // z [M, HD]
                            const float* __restrict__ B,   // WO [DD, HD]
                            float* __restrict__ C,         // out [M, DD]
                            int M) {
    __shared__ float As[2][TBM][TSTR];
    __shared__ float Bs[2][TBN][TSTR];

    const int tid  = threadIdx.x;
    const int warp = tid >> 5;
    const int lane = tid & 31;
    const int g    = lane >> 2;
    const int tg   = lane & 3;
    const int warpM = warp & 3;
    const int warpN = warp >> 2;

    const int bm = blockIdx.y * TBM;
    const int bn = blockIdx.x * TBN;

    float acc[2][4][4];
#pragma unroll
    for (int mt = 0; mt < 2; mt++)
#pragma unroll
        for (int nt = 0; nt < 4; nt++)
#pragma unroll
            for (int c = 0; c < 4; c++) acc[mt][nt][c] = 0.f;

    auto stage = [&](int st, int k0) {
#pragma unroll
        for (int i = 0; i < 4; i++) {
            int idx = tid + i * 256;
            int row = idx >> 3;
            int kc  = (idx & 7) << 2;
            int gr  = bm + row;
            cp_async16(&As[st][row][kc], A + (size_t)gr * HD + k0 + kc, gr < M);
        }
#pragma unroll
        for (int i = 0; i < 2; i++) {
            int idx = tid + i * 256;
            int col = idx >> 3;
            int kc  = (idx & 7) << 2;
            cp_async16(&Bs[st][col][kc], B + (size_t)(bn + col) * HD + k0 + kc, true);
        }
        asm volatile("cp.async.commit_group;");
    };

    const int KT = HD / TBK;   // 8
    stage(0, 0);

    for (int kt = 0; kt < KT; kt++) {
        if (kt + 1 < KT) {
            stage((kt + 1) & 1, (kt + 1) * TBK);
            asm volatile("cp.async.wait_group 1;");
        } else {
            asm volatile("cp.async.wait_group 0;");
        }
        __syncthreads();

        int st = kt & 1;
#pragma unroll
        for (int ks = 0; ks < TBK / 8; ks++) {
            int kb = ks * 8;
            uint32_t afb[2][4], afs[2][4];
#pragma unroll
            for (int mt = 0; mt < 2; mt++) {
                int m0 = warpM * 32 + mt * 16;
                float x0 = As[st][m0 + g    ][kb + tg    ];
                float x1 = As[st][m0 + g + 8][kb + tg    ];
                float x2 = As[st][m0 + g    ][kb + tg + 4];
                float x3 = As[st][m0 + g + 8][kb + tg + 4];
                afb[mt][0] = f2tf32(x0); afs[mt][0] = f2tf32(x0 - __uint_as_float(afb[mt][0]));
                afb[mt][1] = f2tf32(x1); afs[mt][1] = f2tf32(x1 - __uint_as_float(afb[mt][1]));
                afb[mt][2] = f2tf32(x2); afs[mt][2] = f2tf32(x2 - __uint_as_float(afb[mt][2]));
                afb[mt][3] = f2tf32(x3); afs[mt][3] = f2tf32(x3 - __uint_as_float(afb[mt][3]));
            }
            uint32_t bfb[4][2], bfs[4][2];
#pragma unroll
            for (int nt = 0; nt < 4; nt++) {
                int n0 = warpN * 32 + nt * 8;
                float y0 = Bs[st][n0 + g][kb + tg    ];
                float y1 = Bs[st][n0 + g][kb + tg + 4];
                bfb[nt][0] = f2tf32(y0); bfs[nt][0] = f2tf32(y0 - __uint_as_float(bfb[nt][0]));
                bfb[nt][1] = f2tf32(y1); bfs[nt][1] = f2tf32(y1 - __uint_as_float(bfb[nt][1]));
            }
#pragma unroll
            for (int mt = 0; mt < 2; mt++)
#pragma unroll
                for (int nt = 0; nt < 4; nt++) {
                    // small terms first, big last (better summation order)
                    MMA_TF32(acc[mt][nt], afb[mt][0], afb[mt][1], afb[mt][2], afb[mt][3],
                             bfs[nt][0], bfs[nt][1]);
                    MMA_TF32(acc[mt][nt], afs[mt][0], afs[mt][1], afs[mt][2], afs[mt][3],
                             bfb[nt][0], bfb[nt][1]);
                    MMA_TF32(acc[mt][nt], afb[mt][0], afb[mt][1], afb[mt][2], afb[mt][3],
                             bfb[nt][0], bfb[nt][1]);
                }
        }
        __syncthreads();
    }

#pragma unroll
    for (int mt = 0; mt < 2; mt++) {
        int row0 = bm + warpM * 32 + mt * 16 + g;
#pragma unroll
        for (int nt = 0; nt < 4; nt++) {
            int col = bn + warpN * 32 + nt * 8 + tg * 2;
            if (row0 < M)
                *(float2*)(C + (size_t)row0 * DD + col) =
                    make_float2(acc[mt][nt][0], acc[mt][nt][1]);
            if (row0 + 8 < M)
                *(float2*)(C + (size_t)(row0 + 8) * DD + col) =
                    make_float2(acc[mt][nt][2], acc[mt][nt][3]);
        }
    }
}

// ---------------- fused attention: single pass, warp per dst node ----------------
__global__ __launch_bounds__(256)
void node_attn_kernel(const float* __restrict__ C,
                      const int* __restrict__ srcrel,
                      const int* __restrict__ rowoff,
                      float* __restrict__ z, int Nn) {
    int n = (blockIdx.x * blockDim.x + threadIdx.x) >> 5;
    int lane = threadIdx.x & 31;
    if (n >= Nn) return;

    int lo = rowoff[n], hi = rowoff[n + 1];

    const float4* qp = (const float4*)(C + (size_t)n * CW) + lane * 2;
    float4 q0 = qp[0], q1 = qp[1];

    float denom = 0.f;
    float z0 = 0.f, z1 = 0.f, z2 = 0.f, z3 = 0.f, z4 = 0.f, z5 = 0.f, z6 = 0.f, z7 = 0.f;

    for (int p = lo; p < hi; p++) {
        int pr = srcrel[p];
        int s = pr & 0xFFFFF;
        int r = pr >> 20;
        const float* base = C + (size_t)s * CW + (r << 8);
        const float4* kp = (const float4*)(base + 256) + lane * 2;
        const float4* vp = (const float4*)(base + 1024) + lane * 2;
        float4 k0 = kp[0], k1 = kp[1];
        float4 v0 = vp[0], v1 = vp[1];

        float acc = q0.x * k0.x + q0.y * k0.y + q0.z * k0.z + q0.w * k0.w
                  + q1.x * k1.x + q1.y * k1.y + q1.z * k1.z + q1.w * k1.w;
#pragma unroll
        for (int off = 8; off > 0; off >>= 1)
            acc += __shfl_xor_sync(0xffffffffu, acc, off);   // per-head (16-lane) sum

        float sc = acc * (1.0f / 16.0f);                     // / sqrt(D*H)
        float rl = fmaxf(sc, 0.0f);
        float nu = rl * rl + 1e-10f;
        denom += nu;

        z0 += nu * v0.x; z1 += nu * v0.y; z2 += nu * v0.z; z3 += nu * v0.w;
        z4 += nu * v1.x; z5 += nu * v1.y; z6 += nu * v1.z; z7 += nu * v1.w;
    }

    float inv = (denom > 0.f) ? (1.0f / denom) : 0.f;
    float4* zp = (float4*)(z + (size_t)n * HD) + lane * 2;
    zp[0] = make_float4(z0 * inv, z1 * inv, z2 * inv, z3 * inv);
    zp[1] = make_float4(z4 * inv, z5 * inv, z6 * inv, z7 * inv);
}

// ---------------- launch ----------------
extern "C" void kernel_launch(void* const* d_in, const int* in_sizes, int n_in,
                              void* d_out, int out_size) {
    const float* nf  = (const float*)d_in[0];
    const float* WQ  = (const float*)d_in[1];
    const float* WK  = (const float*)d_in[2];
    const float* WV  = (const float*)d_in[3];
    const float* WO  = (const float*)d_in[4];
    const int* esrc  = (const int*)d_in[5];
    const int* edst  = (const int*)d_in[6];
    const int* erel  = (const int*)d_in[7];
    float* out = (float*)d_out;

    float *C, *z;
    int *counts, *rowoff, *cursor, *eidx, *srcrel;
    cudaGetSymbolAddress((void**)&C,      g_C);
    cudaGetSymbolAddress((void**)&z,      g_z);
    cudaGetSymbolAddress((void**)&counts, g_counts);
    cudaGetSymbolAddress((void**)&rowoff, g_rowoff);
    cudaGetSymbolAddress((void**)&cursor, g_cursor);
    cudaGetSymbolAddress((void**)&eidx,   g_eidx);
    cudaGetSymbolAddress((void**)&srcrel, g_srcrel);

    const int E = in_sizes[5];
    const int M = in_sizes[0] / DD;   // = N

    // --- CSR build over edge_dst ---
    zero_int_kernel<<<(M + 255) / 256, 256>>>(counts, M);
    hist_kernel<<<(E + 255) / 256, 256>>>(edst, counts, E);
    scan_kernel<<<1, 1024>>>(counts, rowoff, cursor, M);
    fill_kernel<<<(E + 255) / 256, 256>>>(edst, cursor, eidx, E);
    sortpack_kernel<<<(M + 255) / 256, 256>>>(rowoff, eidx, esrc, erel, srcrel, M);

    // --- fused QKV projection (tf32, double-buffered, one launch) ---
    {
        dim3 blk(256);
        dim3 grd(28, (M + TBM - 1) / TBM);   // 28 = (256+768+768)/64
        gemm_qkv_tf32_kernel<<<grd, blk>>>(nf, WQ, WK, WV, C, M);
    }

    // --- fused single-pass attention (atomic-free, deterministic) ---
    node_attn_kernel<<<(M * 32 + 255) / 256, 256>>>(C, srcrel, rowoff, z, M);

    // --- output projection (3xTF32 tensor cores, fp32-level accuracy) ---
    {
        dim3 blk(256);
        dim3 go(DD / TBN, (M + TBM - 1) / TBM);   // (2, 157)
        gemm_out_tf32x3_kernel<<<go, blk>>>(z, WO, out, M);
    }
}